// round 1
// baseline (speedup 1.0000x reference)
#include <cuda_runtime.h>
#include <math.h>

#define N_TOKENS 16384
#define HIDDEN   1024
#define FFN      4096
#define NEXP     8
#define NSLOTS   (N_TOKENS * 2)

// ---------------- scratch (device globals: the sanctioned no-alloc workaround) ----
__device__ float g_h[(size_t)NSLOTS * FFN];      // 512 MB: relu(x@W1+b1) per slot
__device__ float g_y[(size_t)NSLOTS * HIDDEN];   // 128 MB: h@W2+b2 per slot
__device__ int   g_tok[NSLOTS];                  // slot -> token id
__device__ int   g_token_e[NSLOTS];              // token*2+k -> expert
__device__ float g_token_w[NSLOTS];              // token*2+k -> combine weight
__device__ int   g_token_slot[NSLOTS];           // token*2+k -> slot
__device__ int   g_count[NEXP];
__device__ int   g_cursor[NEXP];
__device__ int   g_offset[NEXP];

// ---------------- reset ------------------------------------------------------------
__global__ void k_reset() {
    int i = threadIdx.x;
    if (i < NEXP) { g_count[i] = 0; g_cursor[i] = 0; }
}

// ---------------- gating: logits, top-2, softmax over the 2, histogram -------------
__global__ void k_gate(const float* __restrict__ x, const float* __restrict__ Wg,
                       const float* __restrict__ bg) {
    int t   = blockIdx.x;
    int tid = threadIdx.x;                 // 128 threads
    float acc[NEXP];
#pragma unroll
    for (int e = 0; e < NEXP; e++) acc[e] = 0.0f;

    const float* xr = x + (size_t)t * HIDDEN;
    for (int k = tid; k < HIDDEN; k += 128) {
        float xv = xr[k];
        const float* wr = Wg + k * NEXP;
#pragma unroll
        for (int e = 0; e < NEXP; e++) acc[e] += xv * wr[e];
    }

    __shared__ float s[128 * NEXP];
#pragma unroll
    for (int e = 0; e < NEXP; e++) s[tid * NEXP + e] = acc[e];
    __syncthreads();

    if (tid < NEXP) {
        float sum = 0.0f;
        for (int r = 0; r < 128; r++) sum += s[r * NEXP + tid];
        s[tid] = sum + bg[tid];            // safe: each thread only reads its own column
    }
    __syncthreads();

    if (tid == 0) {
        // top-2, lowest index wins ties (matches jax.lax.top_k)
        float best = -INFINITY; int e0 = 0;
#pragma unroll
        for (int e = 0; e < NEXP; e++) if (s[e] > best) { best = s[e]; e0 = e; }
        float best2 = -INFINITY; int e1 = 0;
#pragma unroll
        for (int e = 0; e < NEXP; e++) if (e != e0 && s[e] > best2) { best2 = s[e]; e1 = e; }

        float w0 = 1.0f;                   // exp(best - best)
        float w1 = expf(best2 - best);
        float inv = 1.0f / (w0 + w1);
        w0 *= inv; w1 *= inv;

        g_token_e[t * 2 + 0] = e0;  g_token_e[t * 2 + 1] = e1;
        g_token_w[t * 2 + 0] = w0;  g_token_w[t * 2 + 1] = w1;
        atomicAdd(&g_count[e0], 1);
        atomicAdd(&g_count[e1], 1);
    }
}

// ---------------- exclusive scan of the 8 expert counts ----------------------------
__global__ void k_scan() {
    if (threadIdx.x == 0) {
        int off = 0;
        for (int e = 0; e < NEXP; e++) { g_offset[e] = off; off += g_count[e]; }
    }
}

// ---------------- scatter tokens into per-expert compact slot ranges ---------------
__global__ void k_scatter() {
    int t = blockIdx.x * blockDim.x + threadIdx.x;
    if (t >= N_TOKENS) return;
#pragma unroll
    for (int k = 0; k < 2; k++) {
        int e    = g_token_e[t * 2 + k];
        int pos  = atomicAdd(&g_cursor[e], 1);
        int slot = g_offset[e] + pos;
        g_tok[slot] = t;
        g_token_slot[t * 2 + k] = slot;
    }
}

// ---------------- tiled fp32 GEMM, 128x128 tile, BK=16, 256 threads, 8x8 micro -----
// GATHER: A rows indirected through g_tok (pass 1); else contiguous slot rows (pass 2)
// grid: x = Ncols/128, y = expert*128 + m_tile
template <bool GATHER, bool RELU>
__global__ void __launch_bounds__(256)
k_gemm(const float* __restrict__ A, const float* __restrict__ Bw,
       const float* __restrict__ bias, float* __restrict__ C,
       int Kdim, int Ncols) {
    int e     = blockIdx.y >> 7;
    int mt    = blockIdx.y & 127;
    int count = g_count[e];
    int m0    = mt * 128;
    if (m0 >= count) return;

    int n0   = blockIdx.x * 128;
    int base = g_offset[e] + m0;
    const float* B    = Bw + (size_t)e * Kdim * Ncols;
    const float* brow = bias + e * Ncols;

    __shared__ float As[16][132];
    __shared__ float Bs[16][132];

    int tid = threadIdx.x;
    int tx  = tid & 15;
    int ty  = tid >> 4;

    // A tile load map: thread loads float4 at (row, kc) for two rows
    int ra0 = tid >> 2;          // 0..63
    int ra1 = ra0 + 64;          // 64..127
    int kca = (tid & 3) * 4;
    bool v0 = (m0 + ra0) < count;
    bool v1 = (m0 + ra1) < count;
    const float* Arow0 = A;      // dummy init
    const float* Arow1 = A;
    if (GATHER) {
        if (v0) Arow0 = A + (size_t)g_tok[base + ra0] * Kdim;
        if (v1) Arow1 = A + (size_t)g_tok[base + ra1] * Kdim;
    } else {
        Arow0 = A + (size_t)(base + ra0) * Kdim;
        Arow1 = A + (size_t)(base + ra1) * Kdim;
    }

    // B tile load map: thread loads float4 at (kb, nc) for two k-rows
    int kb0 = tid >> 5;          // 0..7
    int kb1 = kb0 + 8;
    int ncb = (tid & 31) * 4;

    float c[8][8];
#pragma unroll
    for (int i = 0; i < 8; i++)
#pragma unroll
        for (int j = 0; j < 8; j++) c[i][j] = 0.0f;

    const float4 z4 = make_float4(0.f, 0.f, 0.f, 0.f);
    float4 ra, rb, rc, rd;

    // prologue: tile 0 -> smem
    ra = v0 ? *(const float4*)(Arow0 + kca) : z4;
    rb = v1 ? *(const float4*)(Arow1 + kca) : z4;
    rc = *(const float4*)(B + (size_t)kb0 * Ncols + n0 + ncb);
    rd = *(const float4*)(B + (size_t)kb1 * Ncols + n0 + ncb);
    As[kca + 0][ra0] = ra.x; As[kca + 1][ra0] = ra.y; As[kca + 2][ra0] = ra.z; As[kca + 3][ra0] = ra.w;
    As[kca + 0][ra1] = rb.x; As[kca + 1][ra1] = rb.y; As[kca + 2][ra1] = rb.z; As[kca + 3][ra1] = rb.w;
    *(float4*)&Bs[kb0][ncb] = rc;
    *(float4*)&Bs[kb1][ncb] = rd;
    __syncthreads();

    int nk = Kdim >> 4;
    for (int kt = 0; kt < nk; kt++) {
        bool more = (kt + 1) < nk;
        if (more) {
            int k0 = (kt + 1) << 4;
            ra = v0 ? *(const float4*)(Arow0 + k0 + kca) : z4;
            rb = v1 ? *(const float4*)(Arow1 + k0 + kca) : z4;
            rc = *(const float4*)(B + (size_t)(k0 + kb0) * Ncols + n0 + ncb);
            rd = *(const float4*)(B + (size_t)(k0 + kb1) * Ncols + n0 + ncb);
        }
#pragma unroll
        for (int k = 0; k < 16; k++) {
            float4 av0 = *(const float4*)&As[k][ty * 8];
            float4 av1 = *(const float4*)&As[k][ty * 8 + 4];
            float4 bv0 = *(const float4*)&Bs[k][tx * 8];
            float4 bv1 = *(const float4*)&Bs[k][tx * 8 + 4];
            float aa[8] = {av0.x, av0.y, av0.z, av0.w, av1.x, av1.y, av1.z, av1.w};
            float bb[8] = {bv0.x, bv0.y, bv0.z, bv0.w, bv1.x, bv1.y, bv1.z, bv1.w};
#pragma unroll
            for (int i = 0; i < 8; i++)
#pragma unroll
                for (int j = 0; j < 8; j++) c[i][j] += aa[i] * bb[j];
        }
        if (more) {
            __syncthreads();
            As[kca + 0][ra0] = ra.x; As[kca + 1][ra0] = ra.y; As[kca + 2][ra0] = ra.z; As[kca + 3][ra0] = ra.w;
            As[kca + 0][ra1] = rb.x; As[kca + 1][ra1] = rb.y; As[kca + 2][ra1] = rb.z; As[kca + 3][ra1] = rb.w;
            *(float4*)&Bs[kb0][ncb] = rc;
            *(float4*)&Bs[kb1][ncb] = rd;
            __syncthreads();
        }
    }

    // epilogue: bias (+relu) and store
#pragma unroll
    for (int i = 0; i < 8; i++) {
        int r = ty * 8 + i;
        if (m0 + r < count) {
            float*       crow = C + (size_t)(base + r) * Ncols + n0 + tx * 8;
            const float* bb   = brow + n0 + tx * 8;
            float4 o0, o1;
            o0.x = c[i][0] + bb[0]; o0.y = c[i][1] + bb[1];
            o0.z = c[i][2] + bb[2]; o0.w = c[i][3] + bb[3];
            o1.x = c[i][4] + bb[4]; o1.y = c[i][5] + bb[5];
            o1.z = c[i][6] + bb[6]; o1.w = c[i][7] + bb[7];
            if (RELU) {
                o0.x = fmaxf(o0.x, 0.f); o0.y = fmaxf(o0.y, 0.f);
                o0.z = fmaxf(o0.z, 0.f); o0.w = fmaxf(o0.w, 0.f);
                o1.x = fmaxf(o1.x, 0.f); o1.y = fmaxf(o1.y, 0.f);
                o1.z = fmaxf(o1.z, 0.f); o1.w = fmaxf(o1.w, 0.f);
            }
            *(float4*)(crow)     = o0;
            *(float4*)(crow + 4) = o1;
        }
    }
}

// ---------------- combine: out[t] = w0*y[slot0] + w1*y[slot1] ----------------------
__global__ void k_combine(float* __restrict__ out) {
    int t  = blockIdx.x;
    int c4 = threadIdx.x;                   // 256 threads, HIDDEN/4 float4s
    int   s0 = g_token_slot[t * 2 + 0];
    int   s1 = g_token_slot[t * 2 + 1];
    float w0 = g_token_w[t * 2 + 0];
    float w1 = g_token_w[t * 2 + 1];
    float4 y0 = ((const float4*)(g_y + (size_t)s0 * HIDDEN))[c4];
    float4 y1 = ((const float4*)(g_y + (size_t)s1 * HIDDEN))[c4];
    float4 o;
    o.x = w0 * y0.x + w1 * y1.x;
    o.y = w0 * y0.y + w1 * y1.y;
    o.z = w0 * y0.z + w1 * y1.z;
    o.w = w0 * y0.w + w1 * y1.w;
    ((float4*)(out + (size_t)t * HIDDEN))[c4] = o;
}

// ---------------- launch -----------------------------------------------------------
extern "C" void kernel_launch(void* const* d_in, const int* in_sizes, int n_in,
                              void* d_out, int out_size) {
    const float* x  = (const float*)d_in[0];
    const float* Wg = (const float*)d_in[1];
    const float* bg = (const float*)d_in[2];
    const float* W1 = (const float*)d_in[3];
    const float* b1 = (const float*)d_in[4];
    const float* W2 = (const float*)d_in[5];
    const float* b2 = (const float*)d_in[6];
    float* out = (float*)d_out;

    float* h_ptr; cudaGetSymbolAddress((void**)&h_ptr, g_h);
    float* y_ptr; cudaGetSymbolAddress((void**)&y_ptr, g_y);

    k_reset<<<1, 32>>>();
    k_gate<<<N_TOKENS, 128>>>(x, Wg, bg);
    k_scan<<<1, 32>>>();
    k_scatter<<<(N_TOKENS + 255) / 256, 256>>>();

    // pass 1: h = relu(gather(x) @ W1[e] + b1[e])   [slots x FFN]
    k_gemm<true, true><<<dim3(FFN / 128, NEXP * 128), 256>>>(
        x, W1, b1, h_ptr, HIDDEN, FFN);

    // pass 2: y = h @ W2[e] + b2[e]                 [slots x HIDDEN]
    k_gemm<false, false><<<dim3(HIDDEN / 128, NEXP * 128), 256>>>(
        h_ptr, W2, b2, y_ptr, FFN, HIDDEN);

    k_combine<<<N_TOKENS, 256>>>(out);
}

// round 3
// speedup vs baseline: 2.3961x; 2.3961x over previous
#include <cuda_runtime.h>
#include <cuda_bf16.h>
#include <math.h>
#include <stdint.h>

#define N_TOKENS 16384
#define HIDDEN   1024
#define FFN      4096
#define NEXP     8
#define NSLOTS   (N_TOKENS * 2)
#define NSLOTS_PAD (NSLOTS + NEXP * 128)   // 33792
#define MAXTILES 272

// ---------------- scratch (device globals) -----------------------------------------
__device__ __nv_bfloat16 g_W1h[(size_t)NEXP * HIDDEN * FFN];   // [e][K][N] hi
__device__ __nv_bfloat16 g_W1l[(size_t)NEXP * HIDDEN * FFN];   // lo
__device__ __nv_bfloat16 g_W2h[(size_t)NEXP * FFN * HIDDEN];
__device__ __nv_bfloat16 g_W2l[(size_t)NEXP * FFN * HIDDEN];
__device__ __nv_bfloat16 g_xh[(size_t)NSLOTS_PAD * HIDDEN];
__device__ __nv_bfloat16 g_xl[(size_t)NSLOTS_PAD * HIDDEN];
__device__ __nv_bfloat16 g_hh[(size_t)NSLOTS_PAD * FFN];
__device__ __nv_bfloat16 g_hl[(size_t)NSLOTS_PAD * FFN];
__device__ float g_y[(size_t)NSLOTS_PAD * HIDDEN];
__device__ int   g_tok[NSLOTS_PAD];
__device__ int   g_token_e[NSLOTS];
__device__ float g_token_w[NSLOTS];
__device__ int   g_token_slot[NSLOTS];
__device__ int   g_count[NEXP], g_cursor[NEXP], g_off_pad[NEXP];
__device__ int   g_tile_e[MAXTILES], g_tile_base[MAXTILES];
__device__ int   g_ntiles, g_npad;

// ---------------- helpers ----------------------------------------------------------
__device__ __forceinline__ uint32_t smem_u32(const void* p) {
    uint32_t a;
    asm("{ .reg .u64 t; cvta.to.shared.u64 t, %1; cvt.u32.u64 %0, t; }" : "=r"(a) : "l"(p));
    return a;
}
__device__ __forceinline__ void cpa16(uint32_t d, const void* s) {
    asm volatile("cp.async.cg.shared.global [%0], [%1], 16;" :: "r"(d), "l"(s));
}
__device__ __forceinline__ void ldm_x4(uint32_t* r, uint32_t a) {
    asm volatile("ldmatrix.sync.aligned.m8n8.x4.shared.b16 {%0,%1,%2,%3}, [%4];"
                 : "=r"(r[0]), "=r"(r[1]), "=r"(r[2]), "=r"(r[3]) : "r"(a));
}
__device__ __forceinline__ void ldm_x4t(uint32_t* r, uint32_t a) {
    asm volatile("ldmatrix.sync.aligned.m8n8.x4.trans.shared.b16 {%0,%1,%2,%3}, [%4];"
                 : "=r"(r[0]), "=r"(r[1]), "=r"(r[2]), "=r"(r[3]) : "r"(a));
}
__device__ __forceinline__ void mma_bf16(float* d, const uint32_t* a, uint32_t b0, uint32_t b1) {
    asm volatile(
        "mma.sync.aligned.m16n8k16.row.col.f32.bf16.bf16.f32 "
        "{%0,%1,%2,%3}, {%4,%5,%6,%7}, {%8,%9}, {%0,%1,%2,%3};"
        : "+f"(d[0]), "+f"(d[1]), "+f"(d[2]), "+f"(d[3])
        : "r"(a[0]), "r"(a[1]), "r"(a[2]), "r"(a[3]), "r"(b0), "r"(b1));
}

// ---------------- reset ------------------------------------------------------------
__global__ void k_reset() {
    int i = threadIdx.x;
    if (i < NEXP) { g_count[i] = 0; g_cursor[i] = 0; }
}

// ---------------- gating -----------------------------------------------------------
__global__ void k_gate(const float* __restrict__ x, const float* __restrict__ Wg,
                       const float* __restrict__ bg) {
    int t   = blockIdx.x;
    int tid = threadIdx.x;
    float acc[NEXP];
#pragma unroll
    for (int e = 0; e < NEXP; e++) acc[e] = 0.0f;
    const float* xr = x + (size_t)t * HIDDEN;
    for (int k = tid; k < HIDDEN; k += 128) {
        float xv = xr[k];
        const float* wr = Wg + k * NEXP;
#pragma unroll
        for (int e = 0; e < NEXP; e++) acc[e] += xv * wr[e];
    }
    __shared__ float s[128 * NEXP];
#pragma unroll
    for (int e = 0; e < NEXP; e++) s[tid * NEXP + e] = acc[e];
    __syncthreads();
    if (tid < NEXP) {
        float sum = 0.0f;
        for (int r = 0; r < 128; r++) sum += s[r * NEXP + tid];
        s[tid] = sum + bg[tid];
    }
    __syncthreads();
    if (tid == 0) {
        float best = -INFINITY; int e0 = 0;
#pragma unroll
        for (int e = 0; e < NEXP; e++) if (s[e] > best) { best = s[e]; e0 = e; }
        float best2 = -INFINITY; int e1 = 0;
#pragma unroll
        for (int e = 0; e < NEXP; e++) if (e != e0 && s[e] > best2) { best2 = s[e]; e1 = e; }
        float w1 = expf(best2 - best);
        float inv = 1.0f / (1.0f + w1);
        g_token_e[t * 2 + 0] = e0;  g_token_e[t * 2 + 1] = e1;
        g_token_w[t * 2 + 0] = inv; g_token_w[t * 2 + 1] = w1 * inv;
        atomicAdd(&g_count[e0], 1);
        atomicAdd(&g_count[e1], 1);
    }
}

// ---------------- scan: padded offsets + tile map ----------------------------------
__global__ void k_scan() {
    if (threadIdx.x != 0) return;
    int off = 0, nt = 0;
    for (int e = 0; e < NEXP; e++) {
        g_off_pad[e] = off;
        int mt = (g_count[e] + 127) >> 7;
        for (int i = 0; i < mt; i++) { g_tile_e[nt] = e; g_tile_base[nt] = off + i * 128; nt++; }
        off += mt * 128;
    }
    g_ntiles = nt; g_npad = off;
}

// ---------------- scatter ----------------------------------------------------------
__global__ void k_scatter() {
    int t = blockIdx.x * blockDim.x + threadIdx.x;
    if (t >= N_TOKENS) return;
#pragma unroll
    for (int k = 0; k < 2; k++) {
        int e    = g_token_e[t * 2 + k];
        int pos  = atomicAdd(&g_cursor[e], 1);
        int slot = g_off_pad[e] + pos;
        g_tok[slot] = t;
        g_token_slot[t * 2 + k] = slot;
    }
}

// ---------------- weight split: fp32 [K][N] -> bf16 hi/lo [K][N] (elementwise) ------
__global__ void k_split(const float* __restrict__ W, __nv_bfloat16* __restrict__ oh,
                        __nv_bfloat16* __restrict__ ol, int n4) {
    int i = blockIdx.x * blockDim.x + threadIdx.x;
    if (i >= n4) return;
    float4 v = ((const float4*)W)[i];
    __nv_bfloat16 h0 = __float2bfloat16(v.x), h1 = __float2bfloat16(v.y);
    __nv_bfloat16 h2 = __float2bfloat16(v.z), h3 = __float2bfloat16(v.w);
    __nv_bfloat162 hh0 = {h0, h1}, hh1 = {h2, h3};
    __nv_bfloat162 ll0 = {__float2bfloat16(v.x - __bfloat162float(h0)),
                          __float2bfloat16(v.y - __bfloat162float(h1))};
    __nv_bfloat162 ll1 = {__float2bfloat16(v.z - __bfloat162float(h2)),
                          __float2bfloat16(v.w - __bfloat162float(h3))};
    ((uint2*)oh)[i] = make_uint2(*(uint32_t*)&hh0, *(uint32_t*)&hh1);
    ((uint2*)ol)[i] = make_uint2(*(uint32_t*)&ll0, *(uint32_t*)&ll1);
}

// ---------------- gather + split x into padded slots --------------------------------
__global__ void k_gather(const float* __restrict__ x) {
    int s = blockIdx.x;
    if (s >= g_npad) return;
    int tile  = s >> 7;
    int e     = g_tile_e[tile];
    int local = s - g_off_pad[e];
    bool real = local < g_count[e];
    int t = real ? g_tok[s] : 0;
    const float* xr = x + (size_t)t * HIDDEN;
    size_t o = (size_t)s * HIDDEN;
    for (int k = threadIdx.x; k < HIDDEN; k += 128) {
        float v = real ? xr[k] : 0.0f;
        __nv_bfloat16 h = __float2bfloat16(v);
        g_xh[o + k] = h;
        g_xl[o + k] = __float2bfloat16(v - __bfloat162float(h));
    }
}

// ---------------- mma.sync bf16 3-term GEMM ----------------------------------------
// block: 256 thr (8 warps, 4m x 2n), tile 128x128, BK=32, 2-stage cp.async.
// A [M][K] row-major hi/lo, B [K][N] row-major hi/lo. D = Ah*Bh + Al*Bh + Ah*Bl.
// smem layout (bytes): [0,512) bias; stages at 512 + s*37888:
//   Ah [128][40]bf16 (10240) | Al (10240) | Bh [32][136]bf16 (8704) | Bl (8704)
// epilogue: Cs f32 [128][132] at offset 512 (reuses stage space).
#define STAGE_B   37888u
#define OFF_AL    10240u
#define OFF_BH    20480u
#define OFF_BL    29184u
#define SMEM_GEMM (512u + 2u * STAGE_B)

template <int KDIM, int NDIM, bool IS_FFN>
__global__ void __launch_bounds__(256) k_gemm(const float* __restrict__ bias) {
    int tile = blockIdx.y;
    if (tile >= g_ntiles) return;
    int e    = g_tile_e[tile];
    int base = g_tile_base[tile];
    int n0   = blockIdx.x * 128;

    extern __shared__ char smem[];
    uint32_t sb = smem_u32(smem);
    float* bs = (float*)smem;
    float* Cs = (float*)(smem + 512);

    int tid  = threadIdx.x;
    int wid  = tid >> 5, lane = tid & 31;
    int wm   = wid & 3, wn = wid >> 2;           // warp tile: rows wm*32, cols wn*64

    const __nv_bfloat16* Ah = IS_FFN ? g_xh : g_hh;
    const __nv_bfloat16* Al = IS_FFN ? g_xl : g_hl;
    const __nv_bfloat16* Bh = (IS_FFN ? g_W1h : g_W2h) + (size_t)e * KDIM * NDIM;
    const __nv_bfloat16* Bl = (IS_FFN ? g_W1l : g_W2l) + (size_t)e * KDIM * NDIM;
    const size_t arow0 = (size_t)base * KDIM;

    if (tid < 128) bs[tid] = bias[(size_t)e * NDIM + n0 + tid];

    // per-thread load maps
    int ar = tid >> 1;                   // A: rows 0..127, 2 chunks each pass
    int aj0 = (tid & 1) * 2;             // chunk 0/2 then +1
    int br = tid >> 3;                   // B: k-rows 0..31
    int bj0 = (tid & 7) * 2;             // n-chunks (16 per row), 2 per thread

    auto load_stage = [&](int st, int kb) {
        uint32_t s0 = sb + 512u + (uint32_t)st * STAGE_B;
        int k0 = kb * 32;
        const __nv_bfloat16* ga = Ah + arow0 + (size_t)ar * KDIM + k0;
        const __nv_bfloat16* gl = Al + arow0 + (size_t)ar * KDIM + k0;
        uint32_t sa = s0 + (uint32_t)ar * 80u;
#pragma unroll
        for (int q = 0; q < 2; q++) {
            int j = aj0 + q;
            cpa16(sa + j * 16u,           ga + j * 8);
            cpa16(sa + OFF_AL + j * 16u,  gl + j * 8);
        }
        const __nv_bfloat16* gb = Bh + (size_t)(k0 + br) * NDIM + n0;
        const __nv_bfloat16* gc = Bl + (size_t)(k0 + br) * NDIM + n0;
        uint32_t sB = s0 + OFF_BH + (uint32_t)br * 272u;
#pragma unroll
        for (int q = 0; q < 2; q++) {
            int j = bj0 + q;
            cpa16(sB + j * 16u,                       gb + j * 8);
            cpa16(sB + (OFF_BL - OFF_BH) + j * 16u,   gc + j * 8);
        }
        asm volatile("cp.async.commit_group;");
    };

    float acc[2][8][4];
#pragma unroll
    for (int i = 0; i < 2; i++)
#pragma unroll
        for (int j = 0; j < 8; j++)
#pragma unroll
            for (int q = 0; q < 4; q++) acc[i][j][q] = 0.0f;

    constexpr int NKB = KDIM / 32;
    load_stage(0, 0);

    // ldmatrix base offsets (within stage)
    int la_row = (lane & 15);            // A: row within 16-row frag
    int la_k8  = (lane >> 4) * 8;
    int lb_k   = (lane & 15);            // B: k-row within 16
    int lb_n8  = (lane >> 4) * 8;

    for (int kb = 0; kb < NKB; kb++) {
        int st = kb & 1;
        if (kb + 1 < NKB) {
            load_stage(st ^ 1, kb + 1);
            asm volatile("cp.async.wait_group 1;");
        } else {
            asm volatile("cp.async.wait_group 0;");
        }
        __syncthreads();

        uint32_t s0 = sb + 512u + (uint32_t)st * STAGE_B;
#pragma unroll
        for (int kk = 0; kk < 32; kk += 16) {
            uint32_t ah[2][4], al[2][4], bh[4][4], bl[4][4];
#pragma unroll
            for (int mi = 0; mi < 2; mi++) {
                uint32_t a = s0 + (uint32_t)(wm * 32 + mi * 16 + la_row) * 80u
                           + (uint32_t)(kk + la_k8) * 2u;
                ldm_x4(ah[mi], a);
                ldm_x4(al[mi], a + OFF_AL);
            }
#pragma unroll
            for (int g = 0; g < 4; g++) {
                uint32_t b = s0 + OFF_BH + (uint32_t)(kk + lb_k) * 272u
                           + (uint32_t)(wn * 64 + g * 16 + lb_n8) * 2u;
                ldm_x4t(bh[g], b);
                ldm_x4t(bl[g], b + (OFF_BL - OFF_BH));
            }
#pragma unroll
            for (int mi = 0; mi < 2; mi++)
#pragma unroll
                for (int g = 0; g < 4; g++) {
                    mma_bf16(acc[mi][2 * g],     ah[mi], bh[g][0], bh[g][1]);
                    mma_bf16(acc[mi][2 * g + 1], ah[mi], bh[g][2], bh[g][3]);
                    mma_bf16(acc[mi][2 * g],     al[mi], bh[g][0], bh[g][1]);
                    mma_bf16(acc[mi][2 * g + 1], al[mi], bh[g][2], bh[g][3]);
                    mma_bf16(acc[mi][2 * g],     ah[mi], bl[g][0], bl[g][1]);
                    mma_bf16(acc[mi][2 * g + 1], ah[mi], bl[g][2], bl[g][3]);
                }
        }
        __syncthreads();
    }

    // stage accums to smem (fp32), then coalesced split stores
#pragma unroll
    for (int mi = 0; mi < 2; mi++) {
        int r0 = wm * 32 + mi * 16 + (lane >> 2);
#pragma unroll
        for (int nf = 0; nf < 8; nf++) {
            int c = wn * 64 + nf * 8 + (lane & 3) * 2;
            Cs[r0 * 132 + c]       = acc[mi][nf][0];
            Cs[r0 * 132 + c + 1]   = acc[mi][nf][1];
            Cs[(r0 + 8) * 132 + c]     = acc[mi][nf][2];
            Cs[(r0 + 8) * 132 + c + 1] = acc[mi][nf][3];
        }
    }
    __syncthreads();

    {
        int row  = tid >> 1;
        int half = tid & 1;
        const float* crow = Cs + row * 132 + half * 64;
        const float* brow = bs + half * 64;
        int grow = base + row;
        if (IS_FFN) {
            size_t o = (size_t)grow * FFN + n0 + half * 64;
#pragma unroll
            for (int j = 0; j < 8; j++) {
                uint32_t ph[4], pl[4];
#pragma unroll
                for (int q = 0; q < 4; q++) {
                    float v0 = fmaxf(crow[j * 8 + 2 * q]     + brow[j * 8 + 2 * q],     0.0f);
                    float v1 = fmaxf(crow[j * 8 + 2 * q + 1] + brow[j * 8 + 2 * q + 1], 0.0f);
                    __nv_bfloat16 h0 = __float2bfloat16(v0), h1 = __float2bfloat16(v1);
                    __nv_bfloat162 vh = {h0, h1};
                    __nv_bfloat162 vl = {__float2bfloat16(v0 - __bfloat162float(h0)),
                                         __float2bfloat16(v1 - __bfloat162float(h1))};
                    ph[q] = *(uint32_t*)&vh;
                    pl[q] = *(uint32_t*)&vl;
                }
                *(uint4*)(g_hh + o + j * 8) = make_uint4(ph[0], ph[1], ph[2], ph[3]);
                *(uint4*)(g_hl + o + j * 8) = make_uint4(pl[0], pl[1], pl[2], pl[3]);
            }
        } else {
            size_t o = (size_t)grow * HIDDEN + n0 + half * 64;
#pragma unroll
            for (int j = 0; j < 16; j++) {
                float4 v;
                v.x = crow[j * 4 + 0] + brow[j * 4 + 0];
                v.y = crow[j * 4 + 1] + brow[j * 4 + 1];
                v.z = crow[j * 4 + 2] + brow[j * 4 + 2];
                v.w = crow[j * 4 + 3] + brow[j * 4 + 3];
                *(float4*)(g_y + o + j * 4) = v;
            }
        }
    }
}

// ---------------- combine ----------------------------------------------------------
__global__ void k_combine(float* __restrict__ out) {
    int t  = blockIdx.x;
    int c4 = threadIdx.x;
    int   s0 = g_token_slot[t * 2 + 0];
    int   s1 = g_token_slot[t * 2 + 1];
    float w0 = g_token_w[t * 2 + 0];
    float w1 = g_token_w[t * 2 + 1];
    float4 y0 = ((const float4*)(g_y + (size_t)s0 * HIDDEN))[c4];
    float4 y1 = ((const float4*)(g_y + (size_t)s1 * HIDDEN))[c4];
    float4 o;
    o.x = w0 * y0.x + w1 * y1.x;
    o.y = w0 * y0.y + w1 * y1.y;
    o.z = w0 * y0.z + w1 * y1.z;
    o.w = w0 * y0.w + w1 * y1.w;
    ((float4*)(out + (size_t)t * HIDDEN))[c4] = o;
}

// ---------------- launch -----------------------------------------------------------
extern "C" void kernel_launch(void* const* d_in, const int* in_sizes, int n_in,
                              void* d_out, int out_size) {
    const float* x  = (const float*)d_in[0];
    const float* Wg = (const float*)d_in[1];
    const float* bg = (const float*)d_in[2];
    const float* W1 = (const float*)d_in[3];
    const float* b1 = (const float*)d_in[4];
    const float* W2 = (const float*)d_in[5];
    const float* b2 = (const float*)d_in[6];
    float* out = (float*)d_out;

    __nv_bfloat16 *w1h, *w1l, *w2h, *w2l;
    cudaGetSymbolAddress((void**)&w1h, g_W1h);
    cudaGetSymbolAddress((void**)&w1l, g_W1l);
    cudaGetSymbolAddress((void**)&w2h, g_W2h);
    cudaGetSymbolAddress((void**)&w2l, g_W2l);

    cudaFuncSetAttribute(k_gemm<HIDDEN, FFN, true>,
                         cudaFuncAttributeMaxDynamicSharedMemorySize, SMEM_GEMM);
    cudaFuncSetAttribute(k_gemm<FFN, HIDDEN, false>,
                         cudaFuncAttributeMaxDynamicSharedMemorySize, SMEM_GEMM);

    k_reset<<<1, 32>>>();
    k_gate<<<N_TOKENS, 128>>>(x, Wg, bg);
    k_scan<<<1, 32>>>();
    k_scatter<<<(N_TOKENS + 255) / 256, 256>>>();

    int n4 = NEXP * HIDDEN * FFN / 4;
    k_split<<<(n4 + 255) / 256, 256>>>(W1, w1h, w1l, n4);
    k_split<<<(n4 + 255) / 256, 256>>>(W2, w2h, w2l, n4);
    k_gather<<<NSLOTS_PAD, 128>>>(x);

    // pass 1: h(hi/lo bf16) = relu(xg @ W1[e] + b1[e])
    k_gemm<HIDDEN, FFN, true><<<dim3(FFN / 128, MAXTILES), 256, SMEM_GEMM>>>(b1);
    // pass 2: y(fp32) = h @ W2[e] + b2[e]
    k_gemm<FFN, HIDDEN, false><<<dim3(HIDDEN / 128, MAXTILES), 256, SMEM_GEMM>>>(b2);

    k_combine<<<N_TOKENS, 256>>>(out);
}

// round 4
// speedup vs baseline: 3.8160x; 1.5926x over previous
#include <cuda_runtime.h>
#include <cuda_fp16.h>
#include <math.h>
#include <stdint.h>

#define N_TOKENS 16384
#define HIDDEN   1024
#define FFN      4096
#define NEXP     8
#define NSLOTS   (N_TOKENS * 2)
#define NSLOTS_PAD (NSLOTS + NEXP * 128)   // 33792
#define MAXTILES 272

// ---------------- scratch (device globals) -----------------------------------------
__device__ __half g_W1h[(size_t)NEXP * HIDDEN * FFN];   // [e][K][N] fp16
__device__ __half g_W2h[(size_t)NEXP * FFN * HIDDEN];
__device__ __half g_xh[(size_t)NSLOTS_PAD * HIDDEN];    // x hi
__device__ __half g_xl[(size_t)NSLOTS_PAD * HIDDEN];    // x lo
__device__ __half g_hh[(size_t)NSLOTS_PAD * FFN];       // h hi
__device__ __half g_hl[(size_t)NSLOTS_PAD * FFN];       // h lo
__device__ float g_y[(size_t)NSLOTS_PAD * HIDDEN];
__device__ int   g_tok[NSLOTS_PAD];
__device__ int   g_token_e[NSLOTS];
__device__ float g_token_w[NSLOTS];
__device__ int   g_token_slot[NSLOTS];
__device__ int   g_count[NEXP], g_cursor[NEXP], g_off_pad[NEXP];
__device__ int   g_tile_e[MAXTILES], g_tile_base[MAXTILES];
__device__ int   g_ntiles, g_npad;

// ---------------- helpers ----------------------------------------------------------
__device__ __forceinline__ uint32_t smem_u32(const void* p) {
    uint32_t a;
    asm("{ .reg .u64 t; cvta.to.shared.u64 t, %1; cvt.u32.u64 %0, t; }" : "=r"(a) : "l"(p));
    return a;
}
__device__ __forceinline__ void cpa16(uint32_t d, const void* s) {
    asm volatile("cp.async.cg.shared.global [%0], [%1], 16;" :: "r"(d), "l"(s));
}
__device__ __forceinline__ void ldm_x4(uint32_t* r, uint32_t a) {
    asm volatile("ldmatrix.sync.aligned.m8n8.x4.shared.b16 {%0,%1,%2,%3}, [%4];"
                 : "=r"(r[0]), "=r"(r[1]), "=r"(r[2]), "=r"(r[3]) : "r"(a));
}
__device__ __forceinline__ void ldm_x4t(uint32_t* r, uint32_t a) {
    asm volatile("ldmatrix.sync.aligned.m8n8.x4.trans.shared.b16 {%0,%1,%2,%3}, [%4];"
                 : "=r"(r[0]), "=r"(r[1]), "=r"(r[2]), "=r"(r[3]) : "r"(a));
}
__device__ __forceinline__ void mma_f16(float* d, const uint32_t* a, uint32_t b0, uint32_t b1) {
    asm volatile(
        "mma.sync.aligned.m16n8k16.row.col.f32.f16.f16.f32 "
        "{%0,%1,%2,%3}, {%4,%5,%6,%7}, {%8,%9}, {%0,%1,%2,%3};"
        : "+f"(d[0]), "+f"(d[1]), "+f"(d[2]), "+f"(d[3])
        : "r"(a[0]), "r"(a[1]), "r"(a[2]), "r"(a[3]), "r"(b0), "r"(b1));
}

// ---------------- reset ------------------------------------------------------------
__global__ void k_reset() {
    int i = threadIdx.x;
    if (i < NEXP) { g_count[i] = 0; g_cursor[i] = 0; }
}

// ---------------- gating -----------------------------------------------------------
__global__ void k_gate(const float* __restrict__ x, const float* __restrict__ Wg,
                       const float* __restrict__ bg) {
    int t   = blockIdx.x;
    int tid = threadIdx.x;
    float acc[NEXP];
#pragma unroll
    for (int e = 0; e < NEXP; e++) acc[e] = 0.0f;
    const float* xr = x + (size_t)t * HIDDEN;
    for (int k = tid; k < HIDDEN; k += 128) {
        float xv = xr[k];
        const float* wr = Wg + k * NEXP;
#pragma unroll
        for (int e = 0; e < NEXP; e++) acc[e] += xv * wr[e];
    }
    __shared__ float s[128 * NEXP];
#pragma unroll
    for (int e = 0; e < NEXP; e++) s[tid * NEXP + e] = acc[e];
    __syncthreads();
    if (tid < NEXP) {
        float sum = 0.0f;
        for (int r = 0; r < 128; r++) sum += s[r * NEXP + tid];
        s[tid] = sum + bg[tid];
    }
    __syncthreads();
    if (tid == 0) {
        float best = -INFINITY; int e0 = 0;
#pragma unroll
        for (int e = 0; e < NEXP; e++) if (s[e] > best) { best = s[e]; e0 = e; }
        float best2 = -INFINITY; int e1 = 0;
#pragma unroll
        for (int e = 0; e < NEXP; e++) if (e != e0 && s[e] > best2) { best2 = s[e]; e1 = e; }
        float w1 = expf(best2 - best);
        float inv = 1.0f / (1.0f + w1);
        g_token_e[t * 2 + 0] = e0;  g_token_e[t * 2 + 1] = e1;
        g_token_w[t * 2 + 0] = inv; g_token_w[t * 2 + 1] = w1 * inv;
        atomicAdd(&g_count[e0], 1);
        atomicAdd(&g_count[e1], 1);
    }
}

// ---------------- scan: padded offsets + tile map ----------------------------------
__global__ void k_scan() {
    if (threadIdx.x != 0) return;
    int off = 0, nt = 0;
    for (int e = 0; e < NEXP; e++) {
        g_off_pad[e] = off;
        int mt = (g_count[e] + 127) >> 7;
        for (int i = 0; i < mt; i++) { g_tile_e[nt] = e; g_tile_base[nt] = off + i * 128; nt++; }
        off += mt * 128;
    }
    g_ntiles = nt; g_npad = off;
}

// ---------------- scatter ----------------------------------------------------------
__global__ void k_scatter() {
    int t = blockIdx.x * blockDim.x + threadIdx.x;
    if (t >= N_TOKENS) return;
#pragma unroll
    for (int k = 0; k < 2; k++) {
        int e    = g_token_e[t * 2 + k];
        int pos  = atomicAdd(&g_cursor[e], 1);
        int slot = g_off_pad[e] + pos;
        g_tok[slot] = t;
        g_token_slot[t * 2 + k] = slot;
    }
}

// ---------------- weight convert: fp32 -> fp16 -------------------------------------
__global__ void k_cvt(const float* __restrict__ W, __half* __restrict__ o, int n4) {
    int i = blockIdx.x * blockDim.x + threadIdx.x;
    if (i >= n4) return;
    float4 v = ((const float4*)W)[i];
    __half2 a = {__float2half_rn(v.x), __float2half_rn(v.y)};
    __half2 b = {__float2half_rn(v.z), __float2half_rn(v.w)};
    ((uint2*)o)[i] = make_uint2(*(uint32_t*)&a, *(uint32_t*)&b);
}

// ---------------- gather + fp16 split x into padded slots ---------------------------
__global__ void k_gather(const float* __restrict__ x) {
    int s = blockIdx.x;
    if (s >= g_npad) return;
    int tile  = s >> 7;
    int e     = g_tile_e[tile];
    int local = s - g_off_pad[e];
    bool real = local < g_count[e];
    int t = real ? g_tok[s] : 0;
    const float* xr = x + (size_t)t * HIDDEN;
    size_t o = (size_t)s * HIDDEN;
    for (int k = threadIdx.x; k < HIDDEN; k += 128) {
        float v = real ? xr[k] : 0.0f;
        __half h = __float2half_rn(v);
        g_xh[o + k] = h;
        g_xl[o + k] = __float2half_rn(v - __half2float(h));
    }
}

// ---------------- mma.sync fp16 2-term GEMM ----------------------------------------
// block: 256 thr (8 warps, 4m x 2n), tile 128x128, BK=32, 3-stage cp.async.
// A [M][K] fp16 hi/lo, B [K][N] fp16. D = Ah*B + Al*B.
// smem (bytes): [0,512) bias; stages at 512 + s*29184:
//   Ah [128][40]h (10240) | Al (10240) | B [32][136]h (8704)
// epilogue: Cs f32 [128][132] at offset 512 (reuses stage space).
#define STAGE_B   29184u
#define OFF_AL    10240u
#define OFF_B     20480u
#define NSTG      3
#define SMEM_GEMM (512u + 3u * STAGE_B)

template <int KDIM, int NDIM, bool IS_FFN>
__global__ void __launch_bounds__(256) k_gemm(const float* __restrict__ bias) {
    int tile = blockIdx.y;
    if (tile >= g_ntiles) return;
    int e    = g_tile_e[tile];
    int base = g_tile_base[tile];
    int n0   = blockIdx.x * 128;

    extern __shared__ char smem[];
    uint32_t sb = smem_u32(smem);
    float* bs = (float*)smem;
    float* Cs = (float*)(smem + 512);

    int tid  = threadIdx.x;
    int wid  = tid >> 5, lane = tid & 31;
    int wm   = wid & 3, wn = wid >> 2;           // warp tile: rows wm*32, cols wn*64

    const __half* Ah = IS_FFN ? g_xh : g_hh;
    const __half* Al = IS_FFN ? g_xl : g_hl;
    const __half* B  = (IS_FFN ? g_W1h : g_W2h) + (size_t)e * KDIM * NDIM;
    const size_t arow0 = (size_t)base * KDIM;

    if (tid < 128) bs[tid] = bias[(size_t)e * NDIM + n0 + tid];

    // load maps
    int ar  = tid >> 1;                  // A rows 0..127
    int aj0 = (tid & 1) * 2;             // 2 of 4 16B-chunks per row
    int br  = tid >> 3;                  // B k-rows 0..31
    int bj0 = (tid & 7) * 2;             // 2 of 16 16B-chunks per row

    auto load_stage = [&](int st, int kb) {
        uint32_t s0 = sb + 512u + (uint32_t)st * STAGE_B;
        int k0 = kb * 32;
        const __half* ga = Ah + arow0 + (size_t)ar * KDIM + k0;
        const __half* gl = Al + arow0 + (size_t)ar * KDIM + k0;
        uint32_t sa = s0 + (uint32_t)ar * 80u;
#pragma unroll
        for (int q = 0; q < 2; q++) {
            int j = aj0 + q;
            cpa16(sa + j * 16u,          ga + j * 8);
            cpa16(sa + OFF_AL + j * 16u, gl + j * 8);
        }
        const __half* gb = B + (size_t)(k0 + br) * NDIM + n0;
        uint32_t sB = s0 + OFF_B + (uint32_t)br * 272u;
#pragma unroll
        for (int q = 0; q < 2; q++) {
            int j = bj0 + q;
            cpa16(sB + j * 16u, gb + j * 8);
        }
        asm volatile("cp.async.commit_group;");
    };

    float acc[2][8][4];
#pragma unroll
    for (int i = 0; i < 2; i++)
#pragma unroll
        for (int j = 0; j < 8; j++)
#pragma unroll
            for (int q = 0; q < 4; q++) acc[i][j][q] = 0.0f;

    constexpr int NKB = KDIM / 32;
    load_stage(0, 0);
    load_stage(1, 1);

    int la_row = (lane & 15);
    int la_k8  = (lane >> 4) * 8;
    int lb_k   = (lane & 15);
    int lb_n8  = (lane >> 4) * 8;

    for (int kb = 0; kb < NKB; kb++) {
        if (kb + 1 < NKB) asm volatile("cp.async.wait_group 1;");
        else              asm volatile("cp.async.wait_group 0;");
        __syncthreads();
        if (kb + 2 < NKB) load_stage((kb + 2) % NSTG, kb + 2);

        uint32_t s0 = sb + 512u + (uint32_t)(kb % NSTG) * STAGE_B;
#pragma unroll
        for (int kk = 0; kk < 32; kk += 16) {
            uint32_t ah[2][4], al[2][4], b[4][4];
#pragma unroll
            for (int mi = 0; mi < 2; mi++) {
                uint32_t a = s0 + (uint32_t)(wm * 32 + mi * 16 + la_row) * 80u
                           + (uint32_t)(kk + la_k8) * 2u;
                ldm_x4(ah[mi], a);
                ldm_x4(al[mi], a + OFF_AL);
            }
#pragma unroll
            for (int g = 0; g < 4; g++) {
                uint32_t bb = s0 + OFF_B + (uint32_t)(kk + lb_k) * 272u
                            + (uint32_t)(wn * 64 + g * 16 + lb_n8) * 2u;
                ldm_x4t(b[g], bb);
            }
#pragma unroll
            for (int mi = 0; mi < 2; mi++)
#pragma unroll
                for (int g = 0; g < 4; g++) {
                    mma_f16(acc[mi][2 * g],     ah[mi], b[g][0], b[g][1]);
                    mma_f16(acc[mi][2 * g + 1], ah[mi], b[g][2], b[g][3]);
                    mma_f16(acc[mi][2 * g],     al[mi], b[g][0], b[g][1]);
                    mma_f16(acc[mi][2 * g + 1], al[mi], b[g][2], b[g][3]);
                }
        }
    }
    __syncthreads();

    // stage accums to smem, then coalesced stores
#pragma unroll
    for (int mi = 0; mi < 2; mi++) {
        int r0 = wm * 32 + mi * 16 + (lane >> 2);
#pragma unroll
        for (int nf = 0; nf < 8; nf++) {
            int c = wn * 64 + nf * 8 + (lane & 3) * 2;
            Cs[r0 * 132 + c]           = acc[mi][nf][0];
            Cs[r0 * 132 + c + 1]       = acc[mi][nf][1];
            Cs[(r0 + 8) * 132 + c]     = acc[mi][nf][2];
            Cs[(r0 + 8) * 132 + c + 1] = acc[mi][nf][3];
        }
    }
    __syncthreads();

    {
        int row  = tid >> 1;
        int half = tid & 1;
        const float* crow = Cs + row * 132 + half * 64;
        const float* brow = bs + half * 64;
        int grow = base + row;
        if (IS_FFN) {
            size_t o = (size_t)grow * FFN + n0 + half * 64;
#pragma unroll
            for (int j = 0; j < 8; j++) {
                uint32_t ph[4], pl[4];
#pragma unroll
                for (int q = 0; q < 4; q++) {
                    float v0 = fmaxf(crow[j * 8 + 2 * q]     + brow[j * 8 + 2 * q],     0.0f);
                    float v1 = fmaxf(crow[j * 8 + 2 * q + 1] + brow[j * 8 + 2 * q + 1], 0.0f);
                    __half h0 = __float2half_rn(v0), h1 = __float2half_rn(v1);
                    __half2 vh = {h0, h1};
                    __half2 vl = {__float2half_rn(v0 - __half2float(h0)),
                                  __float2half_rn(v1 - __half2float(h1))};
                    ph[q] = *(uint32_t*)&vh;
                    pl[q] = *(uint32_t*)&vl;
                }
                *(uint4*)(g_hh + o + j * 8) = make_uint4(ph[0], ph[1], ph[2], ph[3]);
                *(uint4*)(g_hl + o + j * 8) = make_uint4(pl[0], pl[1], pl[2], pl[3]);
            }
        } else {
            size_t o = (size_t)grow * HIDDEN + n0 + half * 64;
#pragma unroll
            for (int j = 0; j < 16; j++) {
                float4 v;
                v.x = crow[j * 4 + 0] + brow[j * 4 + 0];
                v.y = crow[j * 4 + 1] + brow[j * 4 + 1];
                v.z = crow[j * 4 + 2] + brow[j * 4 + 2];
                v.w = crow[j * 4 + 3] + brow[j * 4 + 3];
                *(float4*)(g_y + o + j * 4) = v;
            }
        }
    }
}

// ---------------- combine ----------------------------------------------------------
__global__ void k_combine(float* __restrict__ out) {
    int t  = blockIdx.x;
    int c4 = threadIdx.x;
    int   s0 = g_token_slot[t * 2 + 0];
    int   s1 = g_token_slot[t * 2 + 1];
    float w0 = g_token_w[t * 2 + 0];
    float w1 = g_token_w[t * 2 + 1];
    float4 y0 = ((const float4*)(g_y + (size_t)s0 * HIDDEN))[c4];
    float4 y1 = ((const float4*)(g_y + (size_t)s1 * HIDDEN))[c4];
    float4 o;
    o.x = w0 * y0.x + w1 * y1.x;
    o.y = w0 * y0.y + w1 * y1.y;
    o.z = w0 * y0.z + w1 * y1.z;
    o.w = w0 * y0.w + w1 * y1.w;
    ((float4*)(out + (size_t)t * HIDDEN))[c4] = o;
}

// ---------------- launch -----------------------------------------------------------
extern "C" void kernel_launch(void* const* d_in, const int* in_sizes, int n_in,
                              void* d_out, int out_size) {
    const float* x  = (const float*)d_in[0];
    const float* Wg = (const float*)d_in[1];
    const float* bg = (const float*)d_in[2];
    const float* W1 = (const float*)d_in[3];
    const float* b1 = (const float*)d_in[4];
    const float* W2 = (const float*)d_in[5];
    const float* b2 = (const float*)d_in[6];
    float* out = (float*)d_out;

    __half *w1h, *w2h;
    cudaGetSymbolAddress((void**)&w1h, g_W1h);
    cudaGetSymbolAddress((void**)&w2h, g_W2h);

    cudaFuncSetAttribute(k_gemm<HIDDEN, FFN, true>,
                         cudaFuncAttributeMaxDynamicSharedMemorySize, SMEM_GEMM);
    cudaFuncSetAttribute(k_gemm<FFN, HIDDEN, false>,
                         cudaFuncAttributeMaxDynamicSharedMemorySize, SMEM_GEMM);

    k_reset<<<1, 32>>>();
    k_gate<<<N_TOKENS, 128>>>(x, Wg, bg);
    k_scan<<<1, 32>>>();
    k_scatter<<<(N_TOKENS + 255) / 256, 256>>>();

    int n4 = NEXP * HIDDEN * FFN / 4;
    k_cvt<<<(n4 + 255) / 256, 256>>>(W1, w1h, n4);
    k_cvt<<<(n4 + 255) / 256, 256>>>(W2, w2h, n4);
    k_gather<<<NSLOTS_PAD, 128>>>(x);

    // pass 1: h(hi/lo fp16) = relu(xg @ W1[e] + b1[e])
    k_gemm<HIDDEN, FFN, true><<<dim3(FFN / 128, MAXTILES), 256, SMEM_GEMM>>>(b1);
    // pass 2: y(fp32) = h @ W2[e] + b2[e]
    k_gemm<FFN, HIDDEN, false><<<dim3(HIDDEN / 128, MAXTILES), 256, SMEM_GEMM>>>(b2);

    k_combine<<<N_TOKENS, 256>>>(out);
}

// round 5
// speedup vs baseline: 5.3339x; 1.3978x over previous
#include <cuda_runtime.h>
#include <cuda_fp16.h>
#include <math.h>
#include <stdint.h>

#define N_TOKENS 16384
#define HIDDEN   1024
#define FFN      4096
#define NEXP     8
#define NSLOTS   (N_TOKENS * 2)
#define NSLOTS_PAD (NSLOTS + NEXP * 128)   // 33792
#define MAXTILES 272

// ---------------- scratch (device globals) -----------------------------------------
__device__ __half g_W1h[(size_t)NEXP * HIDDEN * FFN];   // [e][K][N] fp16
__device__ __half g_W2h[(size_t)NEXP * FFN * HIDDEN];
__device__ __half g_xh[(size_t)NSLOTS_PAD * HIDDEN];    // gathered x fp16
__device__ __half g_hh[(size_t)NSLOTS_PAD * FFN];       // h fp16
__device__ float g_y[(size_t)NSLOTS_PAD * HIDDEN];
__device__ int   g_tok[NSLOTS_PAD];
__device__ int   g_token_e[NSLOTS];
__device__ float g_token_w[NSLOTS];
__device__ int   g_token_slot[NSLOTS];
__device__ int   g_count[NEXP], g_cursor[NEXP], g_off_pad[NEXP];
__device__ int   g_tile_e[MAXTILES], g_tile_base[MAXTILES];
__device__ int   g_ntiles, g_npad;

// ---------------- helpers ----------------------------------------------------------
__device__ __forceinline__ uint32_t smem_u32(const void* p) {
    uint32_t a;
    asm("{ .reg .u64 t; cvta.to.shared.u64 t, %1; cvt.u32.u64 %0, t; }" : "=r"(a) : "l"(p));
    return a;
}
__device__ __forceinline__ void cpa16(uint32_t d, const void* s) {
    asm volatile("cp.async.cg.shared.global [%0], [%1], 16;" :: "r"(d), "l"(s));
}
__device__ __forceinline__ void ldm_x4(uint32_t* r, uint32_t a) {
    asm volatile("ldmatrix.sync.aligned.m8n8.x4.shared.b16 {%0,%1,%2,%3}, [%4];"
                 : "=r"(r[0]), "=r"(r[1]), "=r"(r[2]), "=r"(r[3]) : "r"(a));
}
__device__ __forceinline__ void ldm_x4t(uint32_t* r, uint32_t a) {
    asm volatile("ldmatrix.sync.aligned.m8n8.x4.trans.shared.b16 {%0,%1,%2,%3}, [%4];"
                 : "=r"(r[0]), "=r"(r[1]), "=r"(r[2]), "=r"(r[3]) : "r"(a));
}
__device__ __forceinline__ void mma_f16(float* d, const uint32_t* a, uint32_t b0, uint32_t b1) {
    asm volatile(
        "mma.sync.aligned.m16n8k16.row.col.f32.f16.f16.f32 "
        "{%0,%1,%2,%3}, {%4,%5,%6,%7}, {%8,%9}, {%0,%1,%2,%3};"
        : "+f"(d[0]), "+f"(d[1]), "+f"(d[2]), "+f"(d[3])
        : "r"(a[0]), "r"(a[1]), "r"(a[2]), "r"(a[3]), "r"(b0), "r"(b1));
}

// ---------------- reset ------------------------------------------------------------
__global__ void k_reset() {
    int i = threadIdx.x;
    if (i < NEXP) { g_count[i] = 0; g_cursor[i] = 0; }
}

// ---------------- gating -----------------------------------------------------------
__global__ void k_gate(const float* __restrict__ x, const float* __restrict__ Wg,
                       const float* __restrict__ bg) {
    int t   = blockIdx.x;
    int tid = threadIdx.x;
    float acc[NEXP];
#pragma unroll
    for (int e = 0; e < NEXP; e++) acc[e] = 0.0f;
    const float* xr = x + (size_t)t * HIDDEN;
    for (int k = tid; k < HIDDEN; k += 128) {
        float xv = xr[k];
        const float* wr = Wg + k * NEXP;
#pragma unroll
        for (int e = 0; e < NEXP; e++) acc[e] += xv * wr[e];
    }
    __shared__ float s[128 * NEXP];
#pragma unroll
    for (int e = 0; e < NEXP; e++) s[tid * NEXP + e] = acc[e];
    __syncthreads();
    if (tid < NEXP) {
        float sum = 0.0f;
        for (int r = 0; r < 128; r++) sum += s[r * NEXP + tid];
        s[tid] = sum + bg[tid];
    }
    __syncthreads();
    if (tid == 0) {
        float best = -INFINITY; int e0 = 0;
#pragma unroll
        for (int e = 0; e < NEXP; e++) if (s[e] > best) { best = s[e]; e0 = e; }
        float best2 = -INFINITY; int e1 = 0;
#pragma unroll
        for (int e = 0; e < NEXP; e++) if (e != e0 && s[e] > best2) { best2 = s[e]; e1 = e; }
        float w1 = expf(best2 - best);
        float inv = 1.0f / (1.0f + w1);
        g_token_e[t * 2 + 0] = e0;  g_token_e[t * 2 + 1] = e1;
        g_token_w[t * 2 + 0] = inv; g_token_w[t * 2 + 1] = w1 * inv;
        atomicAdd(&g_count[e0], 1);
        atomicAdd(&g_count[e1], 1);
    }
}

// ---------------- scan: padded offsets + tile map ----------------------------------
__global__ void k_scan() {
    if (threadIdx.x != 0) return;
    int off = 0, nt = 0;
    for (int e = 0; e < NEXP; e++) {
        g_off_pad[e] = off;
        int mt = (g_count[e] + 127) >> 7;
        for (int i = 0; i < mt; i++) { g_tile_e[nt] = e; g_tile_base[nt] = off + i * 128; nt++; }
        off += mt * 128;
    }
    g_ntiles = nt; g_npad = off;
}

// ---------------- scatter ----------------------------------------------------------
__global__ void k_scatter() {
    int t = blockIdx.x * blockDim.x + threadIdx.x;
    if (t >= N_TOKENS) return;
#pragma unroll
    for (int k = 0; k < 2; k++) {
        int e    = g_token_e[t * 2 + k];
        int pos  = atomicAdd(&g_cursor[e], 1);
        int slot = g_off_pad[e] + pos;
        g_tok[slot] = t;
        g_token_slot[t * 2 + k] = slot;
    }
}

// ---------------- weight convert: fp32 -> fp16 -------------------------------------
__global__ void k_cvt(const float* __restrict__ W, __half* __restrict__ o, int n4) {
    int i = blockIdx.x * blockDim.x + threadIdx.x;
    if (i >= n4) return;
    float4 v = ((const float4*)W)[i];
    __half2 a = {__float2half_rn(v.x), __float2half_rn(v.y)};
    __half2 b = {__float2half_rn(v.z), __float2half_rn(v.w)};
    ((uint2*)o)[i] = make_uint2(*(uint32_t*)&a, *(uint32_t*)&b);
}

// ---------------- gather x (fp16) into padded slots ---------------------------------
__global__ void k_gather(const float* __restrict__ x) {
    int s = blockIdx.x;
    if (s >= g_npad) return;
    int tile  = s >> 7;
    int e     = g_tile_e[tile];
    int local = s - g_off_pad[e];
    bool real = local < g_count[e];
    int t = real ? g_tok[s] : 0;
    const float* xr = x + (size_t)t * HIDDEN;
    size_t o = (size_t)s * HIDDEN;
    for (int k = threadIdx.x; k < HIDDEN; k += 128) {
        float v = real ? xr[k] : 0.0f;
        g_xh[o + k] = __float2half_rn(v);
    }
}

// ---------------- mma.sync fp16 GEMM -----------------------------------------------
// block: 256 thr (8 warps, 4m x 2n), tile 128x256, BK=32, 3-stage cp.async.
// A [M][K] fp16, B [K][N] fp16. warp tile 32x128.
// smem (bytes): [0,1024) bias(256 f32); stages at 1024 + s*27136:
//   A [128][40]h (10240) | B [32][264]h (16896)
#define STAGE_B   27136u
#define OFF_B     10240u
#define NSTG      3
#define SMEM_GEMM (1024u + 3u * STAGE_B)

template <int KDIM, int NDIM, bool IS_FFN>
__global__ void __launch_bounds__(256, 1) k_gemm(const float* __restrict__ bias) {
    int tile = blockIdx.y;
    if (tile >= g_ntiles) return;
    int e    = g_tile_e[tile];
    int base = g_tile_base[tile];
    int n0   = blockIdx.x * 256;

    extern __shared__ char smem[];
    uint32_t sb = smem_u32(smem);
    float* bs = (float*)smem;

    int tid  = threadIdx.x;
    int wid  = tid >> 5, lane = tid & 31;
    int wm   = wid & 3, wn = wid >> 2;           // warp tile: rows wm*32, cols wn*128

    const __half* A = IS_FFN ? g_xh : g_hh;
    const __half* B = (IS_FFN ? g_W1h : g_W2h) + (size_t)e * KDIM * NDIM;
    const size_t arow0 = (size_t)base * KDIM;

    bs[tid] = bias[(size_t)e * NDIM + n0 + tid];

    // load maps: A 128 rows x 4 chunks (2 thr/row, 2 chunks each);
    //            B 32 rows x 32 chunks (8 thr/row, 4 chunks each)
    int ar  = tid >> 1;
    int aj0 = (tid & 1) * 2;
    int br  = tid >> 3;
    int bj0 = (tid & 7) * 4;

    auto load_stage = [&](int st, int kb) {
        uint32_t s0 = sb + 1024u + (uint32_t)st * STAGE_B;
        int k0 = kb * 32;
        const __half* ga = A + arow0 + (size_t)ar * KDIM + k0;
        uint32_t sa = s0 + (uint32_t)ar * 80u;
#pragma unroll
        for (int q = 0; q < 2; q++) {
            int j = aj0 + q;
            cpa16(sa + j * 16u, ga + j * 8);
        }
        const __half* gb = B + (size_t)(k0 + br) * NDIM + n0;
        uint32_t sB = s0 + OFF_B + (uint32_t)br * 528u;
#pragma unroll
        for (int q = 0; q < 4; q++) {
            int j = bj0 + q;
            cpa16(sB + j * 16u, gb + j * 8);
        }
        asm volatile("cp.async.commit_group;");
    };

    float acc[2][16][4];
#pragma unroll
    for (int i = 0; i < 2; i++)
#pragma unroll
        for (int j = 0; j < 16; j++)
#pragma unroll
            for (int q = 0; q < 4; q++) acc[i][j][q] = 0.0f;

    constexpr int NKB = KDIM / 32;
    load_stage(0, 0);
    load_stage(1, 1);

    int la_row = (lane & 15);
    int la_k8  = (lane >> 4) * 8;
    int lb_k   = (lane & 15);
    int lb_n8  = (lane >> 4) * 8;

    for (int kb = 0; kb < NKB; kb++) {
        if (kb + 1 < NKB) asm volatile("cp.async.wait_group 1;");
        else              asm volatile("cp.async.wait_group 0;");
        __syncthreads();
        if (kb + 2 < NKB) load_stage((kb + 2) % NSTG, kb + 2);

        uint32_t s0 = sb + 1024u + (uint32_t)(kb % NSTG) * STAGE_B;
#pragma unroll
        for (int kk = 0; kk < 32; kk += 16) {
            uint32_t ah[2][4], b[8][4];
#pragma unroll
            for (int mi = 0; mi < 2; mi++) {
                uint32_t a = s0 + (uint32_t)(wm * 32 + mi * 16 + la_row) * 80u
                           + (uint32_t)(kk + la_k8) * 2u;
                ldm_x4(ah[mi], a);
            }
#pragma unroll
            for (int g = 0; g < 8; g++) {
                uint32_t bb = s0 + OFF_B + (uint32_t)(kk + lb_k) * 528u
                            + (uint32_t)(wn * 128 + g * 16 + lb_n8) * 2u;
                ldm_x4t(b[g], bb);
            }
#pragma unroll
            for (int mi = 0; mi < 2; mi++)
#pragma unroll
                for (int g = 0; g < 8; g++) {
                    mma_f16(acc[mi][2 * g],     ah[mi], b[g][0], b[g][1]);
                    mma_f16(acc[mi][2 * g + 1], ah[mi], b[g][2], b[g][3]);
                }
        }
    }
    __syncthreads();

    // direct epilogue from fragments: rows r0/r0+8, cols c,c+1 per (nf)
    {
        int rbase = wm * 32 + (lane >> 2);
        int cbase = wn * 128 + (lane & 3) * 2;
#pragma unroll
        for (int mi = 0; mi < 2; mi++) {
            int r0 = base + rbase + mi * 16;
#pragma unroll
            for (int nf = 0; nf < 16; nf++) {
                int c = cbase + nf * 8;
                float b0 = bs[c], b1 = bs[c + 1];
                if (IS_FFN) {
                    float v0 = fmaxf(acc[mi][nf][0] + b0, 0.0f);
                    float v1 = fmaxf(acc[mi][nf][1] + b1, 0.0f);
                    float v2 = fmaxf(acc[mi][nf][2] + b0, 0.0f);
                    float v3 = fmaxf(acc[mi][nf][3] + b1, 0.0f);
                    __half2 p0 = {__float2half_rn(v0), __float2half_rn(v1)};
                    __half2 p1 = {__float2half_rn(v2), __float2half_rn(v3)};
                    *(__half2*)(g_hh + (size_t)r0 * FFN + n0 + c)       = p0;
                    *(__half2*)(g_hh + (size_t)(r0 + 8) * FFN + n0 + c) = p1;
                } else {
                    float2 p0 = {acc[mi][nf][0] + b0, acc[mi][nf][1] + b1};
                    float2 p1 = {acc[mi][nf][2] + b0, acc[mi][nf][3] + b1};
                    *(float2*)(g_y + (size_t)r0 * HIDDEN + n0 + c)       = p0;
                    *(float2*)(g_y + (size_t)(r0 + 8) * HIDDEN + n0 + c) = p1;
                }
            }
        }
    }
}

// ---------------- combine ----------------------------------------------------------
__global__ void k_combine(float* __restrict__ out) {
    int t  = blockIdx.x;
    int c4 = threadIdx.x;
    int   s0 = g_token_slot[t * 2 + 0];
    int   s1 = g_token_slot[t * 2 + 1];
    float w0 = g_token_w[t * 2 + 0];
    float w1 = g_token_w[t * 2 + 1];
    float4 y0 = ((const float4*)(g_y + (size_t)s0 * HIDDEN))[c4];
    float4 y1 = ((const float4*)(g_y + (size_t)s1 * HIDDEN))[c4];
    float4 o;
    o.x = w0 * y0.x + w1 * y1.x;
    o.y = w0 * y0.y + w1 * y1.y;
    o.z = w0 * y0.z + w1 * y1.z;
    o.w = w0 * y0.w + w1 * y1.w;
    ((float4*)(out + (size_t)t * HIDDEN))[c4] = o;
}

// ---------------- launch -----------------------------------------------------------
extern "C" void kernel_launch(void* const* d_in, const int* in_sizes, int n_in,
                              void* d_out, int out_size) {
    const float* x  = (const float*)d_in[0];
    const float* Wg = (const float*)d_in[1];
    const float* bg = (const float*)d_in[2];
    const float* W1 = (const float*)d_in[3];
    const float* b1 = (const float*)d_in[4];
    const float* W2 = (const float*)d_in[5];
    const float* b2 = (const float*)d_in[6];
    float* out = (float*)d_out;

    __half *w1h, *w2h;
    cudaGetSymbolAddress((void**)&w1h, g_W1h);
    cudaGetSymbolAddress((void**)&w2h, g_W2h);

    cudaFuncSetAttribute(k_gemm<HIDDEN, FFN, true>,
                         cudaFuncAttributeMaxDynamicSharedMemorySize, SMEM_GEMM);
    cudaFuncSetAttribute(k_gemm<FFN, HIDDEN, false>,
                         cudaFuncAttributeMaxDynamicSharedMemorySize, SMEM_GEMM);

    k_reset<<<1, 32>>>();
    k_gate<<<N_TOKENS, 128>>>(x, Wg, bg);
    k_scan<<<1, 32>>>();
    k_scatter<<<(N_TOKENS + 255) / 256, 256>>>();

    int n4 = NEXP * HIDDEN * FFN / 4;
    k_cvt<<<(n4 + 255) / 256, 256>>>(W1, w1h, n4);
    k_cvt<<<(n4 + 255) / 256, 256>>>(W2, w2h, n4);
    k_gather<<<NSLOTS_PAD, 128>>>(x);

    // pass 1: h(fp16) = relu(xg @ W1[e] + b1[e])
    k_gemm<HIDDEN, FFN, true><<<dim3(FFN / 256, MAXTILES), 256, SMEM_GEMM>>>(b1);
    // pass 2: y(fp32) = h @ W2[e] + b2[e]
    k_gemm<FFN, HIDDEN, false><<<dim3(HIDDEN / 256, MAXTILES), 256, SMEM_GEMM>>>(b2);

    k_combine<<<N_TOKENS, 256>>>(out);
}